// round 8
// baseline (speedup 1.0000x reference)
#include <cuda_runtime.h>

// GraphSAGE 3-layer, GB300 sm_103a.
// Round 8 (resubmit; R7 died on device-busy before any kernel ran; the
// err-717 fix from R4 is STILL untested):
// device-side edge dtype detection + clamped int32 decode,
// then CSR build + warp-gather aggregation + fp32 SIMT dual-GEMM.

#define NND 50000
#define NED 800000

// ---------------- scratch (static device globals; no allocation) -------------
__device__ int   g_is64;
__device__ int   g_src32[NED];
__device__ int   g_dst32[NED];
__device__ int   g_deg[NND];
__device__ int   g_off[NND];
__device__ int   g_cur[NND];
__device__ float g_inv[NND];
__device__ int   g_srcs[NED];
__device__ float g_mean[(size_t)NND * 256];
__device__ float g_h1[(size_t)NND * 256];
__device__ float g_h2[(size_t)NND * 256];

// buffer selector: 0 = external pointer, 1 = g_mean, 2 = g_h1, 3 = g_h2
__device__ __forceinline__ float* sel_buf(int sel, const float* ext)
{
    switch (sel) {
        case 1:  return g_mean;
        case 2:  return g_h1;
        case 3:  return g_h2;
        default: return (float*)ext;
    }
}

// ---------------- edge-index dtype detect + decode ---------------------------
// If the buffer holds int64 values < 2^31, every odd int32 word (the high
// half) is 0. If it holds int32 node ids (random in [0, 50000)), the odd
// words are ordinary indices and are ~never all zero across 1024 samples.
__global__ void k_detect(const int* __restrict__ base)
{
    if (blockIdx.x == 0 && threadIdx.x == 0) {
        int nz = 0;
        for (int i = 0; i < 1024; i++) nz += (base[2 * i + 1] != 0);
        g_is64 = (nz == 0) ? 1 : 0;
    }
}

__global__ void k_decode(const void* __restrict__ eiv)
{
    int e = blockIdx.x * blockDim.x + threadIdx.x;
    if (e >= NED) return;
    int s, d;
    if (g_is64) {
        const long long* p = (const long long*)eiv;
        s = (int)p[e];
        d = (int)p[e + NED];
    } else {
        const int* p = (const int*)eiv;
        s = p[e];
        d = p[e + NED];
    }
    // clamp so no downstream access can ever trap
    s = min(max(s, 0), NND - 1);
    d = min(max(d, 0), NND - 1);
    g_src32[e] = s;
    g_dst32[e] = d;
}

// ---------------- CSR build --------------------------------------------------
__global__ void k_init()
{
    int i = blockIdx.x * blockDim.x + threadIdx.x;
    if (i < NND) { g_deg[i] = 0; g_cur[i] = 0; }
}

__global__ void k_count()
{
    int e = blockIdx.x * blockDim.x + threadIdx.x;
    if (e < NED) atomicAdd(&g_deg[g_dst32[e]], 1);
}

// single-block exclusive scan over g_deg -> g_off, and g_inv = 1/max(deg,1)
__global__ __launch_bounds__(1024)
void k_scan()
{
    __shared__ int s[1024];
    __shared__ int carry;
    if (threadIdx.x == 0) carry = 0;
    __syncthreads();
    for (int base = 0; base < NND; base += 1024) {
        int i = base + (int)threadIdx.x;
        int v = (i < NND) ? g_deg[i] : 0;
        s[threadIdx.x] = v;
        __syncthreads();
        for (int o = 1; o < 1024; o <<= 1) {
            int t = (threadIdx.x >= (unsigned)o) ? s[threadIdx.x - o] : 0;
            __syncthreads();
            s[threadIdx.x] += t;
            __syncthreads();
        }
        int incl = s[threadIdx.x];
        int c = carry;
        if (i < NND) {
            g_off[i] = c + incl - v;
            g_inv[i] = (v > 0) ? (1.0f / (float)v) : 0.0f;
        }
        __syncthreads();
        if (threadIdx.x == 0) carry = c + s[1023];
        __syncthreads();
    }
}

__global__ void k_fill()
{
    int e = blockIdx.x * blockDim.x + threadIdx.x;
    if (e < NED) {
        int d = g_dst32[e];
        int p = atomicAdd(&g_cur[d], 1);
        g_srcs[g_off[d] + p] = g_src32[e];
    }
}

// ---------------- aggregation: warp-per-node mean over in-neighbors ----------
// DV = row width in float4 (32 -> d=128, 64 -> d=256)
template <int DV>
__global__ void k_aggregate(const float* __restrict__ ext_in,
                            int in_sel, int out_sel)
{
    int warp = (blockIdx.x * blockDim.x + threadIdx.x) >> 5;
    if (warp >= NND) return;
    int lane = threadIdx.x & 31;
    int beg  = g_off[warp];
    int dg   = g_deg[warp];

    const float* feat    = sel_buf(in_sel, ext_in);
    float*       meanout = sel_buf(out_sel, nullptr);

    float4 a0 = make_float4(0.f, 0.f, 0.f, 0.f);
    float4 a1 = make_float4(0.f, 0.f, 0.f, 0.f);
    const float4* f4 = (const float4*)feat;

    for (int t = 0; t < dg; t++) {
        int s = g_srcs[beg + t];             // broadcast across warp
        const float4* row = f4 + (size_t)s * DV;
        float4 v = row[lane];
        a0.x += v.x; a0.y += v.y; a0.z += v.z; a0.w += v.w;
        if (DV == 64) {
            float4 w = row[lane + 32];
            a1.x += w.x; a1.y += w.y; a1.z += w.z; a1.w += w.w;
        }
    }
    float inv = g_inv[warp];
    a0.x *= inv; a0.y *= inv; a0.z *= inv; a0.w *= inv;
    float4* mo = (float4*)meanout + (size_t)warp * DV;
    mo[lane] = a0;
    if (DV == 64) {
        a1.x *= inv; a1.y *= inv; a1.z *= inv; a1.w *= inv;
        mo[lane + 32] = a1;
    }
}

// ---------------- dual GEMM: out = A0@B0 + A1@B1 + bias (opt relu) -----------
// A0 = sel_buf(a0_sel), A1 = sel_buf(a1_sel, ext_a1): [NND, K] row-major.
// B0, B1: [K, NC] row-major (weights, external).  out: [NND, NC].
// Tiles: BM=64, BN=64, BK=16; 256 threads; 4x4 accum per thread.
__global__ __launch_bounds__(256)
void k_gemm_dual(int a0_sel, const float* __restrict__ ext_a1, int a1_sel,
                 const float* __restrict__ B0, const float* __restrict__ B1,
                 const float* __restrict__ bias,
                 float* __restrict__ ext_out, int out_sel,
                 int K, int NC, int relu)
{
    __shared__ float As[16][64];
    __shared__ float Bs[16][64];

    const float* A0  = sel_buf(a0_sel, nullptr);
    const float* A1  = sel_buf(a1_sel, ext_a1);
    float*       out = sel_buf(out_sel, ext_out);

    int tid = threadIdx.x;
    int tx = tid & 15;        // 0..15 -> col group
    int ty = tid >> 4;        // 0..15 -> row group
    int rowBase = blockIdx.x * 64;
    int colBase = blockIdx.y * 64;

    float acc[4][4];
#pragma unroll
    for (int i = 0; i < 4; i++)
#pragma unroll
        for (int j = 0; j < 4; j++) acc[i][j] = 0.f;

    int a_r  = tid >> 2;          // 0..63 tile row
    int a_k4 = (tid & 3) * 4;     // k offset (float4)
    int b_k  = tid >> 4;          // 0..15 tile k
    int b_c4 = (tid & 15) * 4;    // col offset (float4)

    for (int kk = 0; kk < 2 * K; kk += 16) {
        const float* A = (kk < K) ? A0 : A1;
        const float* B = (kk < K) ? B0 : B1;
        int k0 = (kk < K) ? kk : (kk - K);

        // A tile (transposed into smem)
        int gr = rowBase + a_r;
        float4 av = make_float4(0.f, 0.f, 0.f, 0.f);
        if (gr < NND)
            av = *(const float4*)(A + (size_t)gr * K + k0 + a_k4);
        As[a_k4 + 0][a_r] = av.x;
        As[a_k4 + 1][a_r] = av.y;
        As[a_k4 + 2][a_r] = av.z;
        As[a_k4 + 3][a_r] = av.w;

        // B tile
        float4 bv = *(const float4*)(B + (size_t)(k0 + b_k) * NC + colBase + b_c4);
        *(float4*)&Bs[b_k][b_c4] = bv;

        __syncthreads();

#pragma unroll
        for (int k = 0; k < 16; k++) {
            float4 ra = *(float4*)&As[k][ty * 4];
            float4 rb = *(float4*)&Bs[k][tx * 4];
            float ar[4] = {ra.x, ra.y, ra.z, ra.w};
            float br[4] = {rb.x, rb.y, rb.z, rb.w};
#pragma unroll
            for (int i = 0; i < 4; i++)
#pragma unroll
                for (int j = 0; j < 4; j++)
                    acc[i][j] += ar[i] * br[j];
        }
        __syncthreads();
    }

#pragma unroll
    for (int i = 0; i < 4; i++) {
        int r = rowBase + ty * 4 + i;
        if (r >= NND) continue;
#pragma unroll
        for (int j = 0; j < 4; j++) {
            int c = colBase + tx * 4 + j;
            float v = acc[i][j] + bias[c];
            if (relu) v = fmaxf(v, 0.f);
            out[(size_t)r * NC + c] = v;
        }
    }
}

// ---------------- launch -----------------------------------------------------
extern "C" void kernel_launch(void* const* d_in, const int* in_sizes, int n_in,
                              void* d_out, int out_size)
{
    const float* x   = (const float*)d_in[0];
    const void*  ei  = d_in[1];
    const float* Wl0 = (const float*)d_in[2];
    const float* b0  = (const float*)d_in[3];
    const float* Wr0 = (const float*)d_in[4];
    const float* Wl1 = (const float*)d_in[5];
    const float* b1  = (const float*)d_in[6];
    const float* Wr1 = (const float*)d_in[7];
    const float* Wl2 = (const float*)d_in[8];
    const float* b2  = (const float*)d_in[9];
    const float* Wr2 = (const float*)d_in[10];
    float* out = (float*)d_out;

    // edge decode (dtype-robust) + CSR build
    k_detect<<<1, 32>>>((const int*)ei);
    k_decode<<<(NED + 255) / 256, 256>>>(ei);
    k_init  <<<(NND + 255) / 256, 256>>>();
    k_count <<<(NED + 255) / 256, 256>>>();
    k_scan  <<<1, 1024>>>();
    k_fill  <<<(NED + 255) / 256, 256>>>();

    const int AGG_BLK = 256;                      // 8 warps / block
    int aggGrid = (NND * 32 + AGG_BLK - 1) / AGG_BLK;

    // layer 0: 128 -> 256, relu.  agg(x) -> g_mean; gemm(g_mean, x) -> g_h1
    k_aggregate<32><<<aggGrid, AGG_BLK>>>(x, 0, 1);
    {
        dim3 g((NND + 63) / 64, 256 / 64);
        k_gemm_dual<<<g, 256>>>(1, x, 0, Wl0, Wr0, b0, nullptr, 2, 128, 256, 1);
    }

    // layer 1: 256 -> 256, relu.  agg(g_h1) -> g_mean; gemm(g_mean, g_h1) -> g_h2
    k_aggregate<64><<<aggGrid, AGG_BLK>>>(nullptr, 2, 1);
    {
        dim3 g((NND + 63) / 64, 256 / 64);
        k_gemm_dual<<<g, 256>>>(1, nullptr, 2, Wl1, Wr1, b1, nullptr, 3, 256, 256, 1);
    }

    // layer 2: 256 -> 128, no relu.  agg(g_h2) -> g_mean; gemm(g_mean, g_h2) -> out
    k_aggregate<64><<<aggGrid, AGG_BLK>>>(nullptr, 3, 1);
    {
        dim3 g((NND + 63) / 64, 128 / 64);
        k_gemm_dual<<<g, 256>>>(1, nullptr, 3, Wl2, Wr2, b2, out, 0, 256, 128, 0);
    }
    (void)in_sizes; (void)n_in; (void)out_size;
}

// round 16
// speedup vs baseline: 1.7005x; 1.7005x over previous
#include <cuda_runtime.h>
#include <cstdint>

// GraphSAGE 3-layer, GB300 sm_103a.
// Round 16 (resubmit; twelve infra failures so far, experiment still untested):
// tf32 mma.sync dual-GEMM + aggregation index-prefetch unroll x4
// (order-preserving, bitwise-identical to the R8 baseline aggregation).

#define NND 50000
#define NED 800000

// ---------------- scratch (static device globals; no allocation) -------------
__device__ int   g_is64;
__device__ int   g_src32[NED];
__device__ int   g_dst32[NED];
__device__ int   g_deg[NND];
__device__ int   g_off[NND];
__device__ int   g_cur[NND];
__device__ float g_inv[NND];
__device__ int   g_srcs[NED];
__device__ float g_mean[(size_t)NND * 256];
__device__ float g_h1[(size_t)NND * 256];
__device__ float g_h2[(size_t)NND * 256];

// buffer selector: 0 = external pointer, 1 = g_mean, 2 = g_h1, 3 = g_h2
__device__ __forceinline__ float* sel_buf(int sel, const float* ext)
{
    switch (sel) {
        case 1:  return g_mean;
        case 2:  return g_h1;
        case 3:  return g_h2;
        default: return (float*)ext;
    }
}

__device__ __forceinline__ float to_tf32(float x)
{
    uint32_t u;
    asm("cvt.rna.tf32.f32 %0, %1;" : "=r"(u) : "f"(x));
    return __uint_as_float(u);
}

// ---------------- edge-index dtype detect + decode ---------------------------
__global__ void k_detect(const int* __restrict__ base)
{
    if (blockIdx.x == 0 && threadIdx.x == 0) {
        int nz = 0;
        for (int i = 0; i < 1024; i++) nz += (base[2 * i + 1] != 0);
        g_is64 = (nz == 0) ? 1 : 0;
    }
}

__global__ void k_decode(const void* __restrict__ eiv)
{
    int e = blockIdx.x * blockDim.x + threadIdx.x;
    if (e >= NED) return;
    int s, d;
    if (g_is64) {
        const long long* p = (const long long*)eiv;
        s = (int)p[e];
        d = (int)p[e + NED];
    } else {
        const int* p = (const int*)eiv;
        s = p[e];
        d = p[e + NED];
    }
    s = min(max(s, 0), NND - 1);
    d = min(max(d, 0), NND - 1);
    g_src32[e] = s;
    g_dst32[e] = d;
}

// ---------------- CSR build --------------------------------------------------
__global__ void k_init()
{
    int i = blockIdx.x * blockDim.x + threadIdx.x;
    if (i < NND) { g_deg[i] = 0; g_cur[i] = 0; }
}

__global__ void k_count()
{
    int e = blockIdx.x * blockDim.x + threadIdx.x;
    if (e < NED) atomicAdd(&g_deg[g_dst32[e]], 1);
}

__global__ __launch_bounds__(1024)
void k_scan()
{
    __shared__ int s[1024];
    __shared__ int carry;
    if (threadIdx.x == 0) carry = 0;
    __syncthreads();
    for (int base = 0; base < NND; base += 1024) {
        int i = base + (int)threadIdx.x;
        int v = (i < NND) ? g_deg[i] : 0;
        s[threadIdx.x] = v;
        __syncthreads();
        for (int o = 1; o < 1024; o <<= 1) {
            int t = (threadIdx.x >= (unsigned)o) ? s[threadIdx.x - o] : 0;
            __syncthreads();
            s[threadIdx.x] += t;
            __syncthreads();
        }
        int incl = s[threadIdx.x];
        int c = carry;
        if (i < NND) {
            g_off[i] = c + incl - v;
            g_inv[i] = (v > 0) ? (1.0f / (float)v) : 0.0f;
        }
        __syncthreads();
        if (threadIdx.x == 0) carry = c + s[1023];
        __syncthreads();
    }
}

__global__ void k_fill()
{
    int e = blockIdx.x * blockDim.x + threadIdx.x;
    if (e < NED) {
        int d = g_dst32[e];
        int p = atomicAdd(&g_cur[d], 1);
        g_srcs[g_off[d] + p] = g_src32[e];
    }
}

// ---------------- aggregation: warp-per-node mean over in-neighbors ----------
// DV = row width in float4 (32 -> d=128, 64 -> d=256).
// Unroll x4 with index prefetch; accumulation order identical to serial loop.
template <int DV>
__global__ void k_aggregate(const float* __restrict__ ext_in,
                            int in_sel, int out_sel)
{
    int warp = (blockIdx.x * blockDim.x + threadIdx.x) >> 5;
    if (warp >= NND) return;
    int lane = threadIdx.x & 31;
    int beg  = g_off[warp];
    int dg   = g_deg[warp];

    const float* feat    = sel_buf(in_sel, ext_in);
    float*       meanout = sel_buf(out_sel, nullptr);

    float4 a0 = make_float4(0.f, 0.f, 0.f, 0.f);
    float4 a1 = make_float4(0.f, 0.f, 0.f, 0.f);
    const float4* f4 = (const float4*)feat;

    int t = 0;
    for (; t + 4 <= dg; t += 4) {
        int s0 = g_srcs[beg + t + 0];
        int s1 = g_srcs[beg + t + 1];
        int s2 = g_srcs[beg + t + 2];
        int s3 = g_srcs[beg + t + 3];
        const float4* r0 = f4 + (size_t)s0 * DV;
        const float4* r1 = f4 + (size_t)s1 * DV;
        const float4* r2 = f4 + (size_t)s2 * DV;
        const float4* r3 = f4 + (size_t)s3 * DV;
        float4 v0 = r0[lane];
        float4 v1 = r1[lane];
        float4 v2 = r2[lane];
        float4 v3 = r3[lane];
        // same order as serial loop: t, t+1, t+2, t+3
        a0.x += v0.x; a0.y += v0.y; a0.z += v0.z; a0.w += v0.w;
        a0.x += v1.x; a0.y += v1.y; a0.z += v1.z; a0.w += v1.w;
        a0.x += v2.x; a0.y += v2.y; a0.z += v2.z; a0.w += v2.w;
        a0.x += v3.x; a0.y += v3.y; a0.z += v3.z; a0.w += v3.w;
        if (DV == 64) {
            float4 w0 = r0[lane + 32];
            float4 w1 = r1[lane + 32];
            float4 w2 = r2[lane + 32];
            float4 w3 = r3[lane + 32];
            a1.x += w0.x; a1.y += w0.y; a1.z += w0.z; a1.w += w0.w;
            a1.x += w1.x; a1.y += w1.y; a1.z += w1.z; a1.w += w1.w;
            a1.x += w2.x; a1.y += w2.y; a1.z += w2.z; a1.w += w2.w;
            a1.x += w3.x; a1.y += w3.y; a1.z += w3.z; a1.w += w3.w;
        }
    }
    for (; t < dg; t++) {
        int s = g_srcs[beg + t];
        const float4* row = f4 + (size_t)s * DV;
        float4 v = row[lane];
        a0.x += v.x; a0.y += v.y; a0.z += v.z; a0.w += v.w;
        if (DV == 64) {
            float4 w = row[lane + 32];
            a1.x += w.x; a1.y += w.y; a1.z += w.z; a1.w += w.w;
        }
    }

    float inv = g_inv[warp];
    a0.x *= inv; a0.y *= inv; a0.z *= inv; a0.w *= inv;
    float4* mo = (float4*)meanout + (size_t)warp * DV;
    mo[lane] = a0;
    if (DV == 64) {
        a1.x *= inv; a1.y *= inv; a1.z *= inv; a1.w *= inv;
        mo[lane + 32] = a1;
    }
}

// ---------------- tf32 tensor-core dual GEMM ---------------------------------
// out = A0@B0 + A1@B1 + bias (opt relu)
// A0/A1: [NND, K] row-major. B0/B1: [K, NC] row-major. out: [NND, NC].
// BM=128, BN=64, BK=16; 256 threads = 8 warps (4 m x 2 n), warp tile 32x32.
// Each warp: 2 (m) x 4 (n) m16n8k8 fragments, 2 k-steps per BK iter.
#define BM 128
#define BN 64
#define BK 16
#define AS_STRIDE (BM + 8)   // 136: 136%32=8 -> frag loads conflict-free
#define BS_STRIDE (BN + 8)   // 72:  72%32=8  -> frag loads conflict-free

__global__ __launch_bounds__(256)
void k_gemm_tc(int a0_sel, const float* __restrict__ ext_a1, int a1_sel,
               const float* __restrict__ B0, const float* __restrict__ B1,
               const float* __restrict__ bias,
               float* __restrict__ ext_out, int out_sel,
               int K, int NC, int relu)
{
    __shared__ float As[BK][AS_STRIDE];
    __shared__ float Bs[BK][BS_STRIDE];

    const float* A0  = sel_buf(a0_sel, nullptr);
    const float* A1  = sel_buf(a1_sel, ext_a1);
    float*       out = sel_buf(out_sel, ext_out);

    const int tid  = threadIdx.x;
    const int wid  = tid >> 5;
    const int lane = tid & 31;
    const int wm   = wid & 3;        // 0..3  -> m offset wm*32
    const int wn   = wid >> 2;       // 0..1  -> n offset wn*32
    const int gid  = lane >> 2;      // 0..7
    const int tig  = lane & 3;       // 0..3

    const int rowBase = blockIdx.x * BM;
    const int colBase = blockIdx.y * BN;

    float acc[2][4][4];
#pragma unroll
    for (int mt = 0; mt < 2; mt++)
#pragma unroll
        for (int nt = 0; nt < 4; nt++)
#pragma unroll
            for (int i = 0; i < 4; i++) acc[mt][nt][i] = 0.f;

    const int b_k  = tid >> 4;            // 0..15
    const int b_n4 = (tid & 15) * 4;      // 0..60

    for (int kk = 0; kk < 2 * K; kk += BK) {
        const float* A = (kk < K) ? A0 : A1;
        const float* B = (kk < K) ? B0 : B1;
        const int k0 = (kk < K) ? kk : (kk - K);

#pragma unroll
        for (int it = 0; it < 2; it++) {
            int elem = tid + 256 * it;        // 0..511
            int row  = elem >> 2;             // 0..127
            int k4   = (elem & 3) * 4;        // 0,4,8,12
            int gr   = rowBase + row;
            float4 av = make_float4(0.f, 0.f, 0.f, 0.f);
            if (gr < NND)
                av = *(const float4*)(A + (size_t)gr * K + k0 + k4);
            As[k4 + 0][row] = to_tf32(av.x);
            As[k4 + 1][row] = to_tf32(av.y);
            As[k4 + 2][row] = to_tf32(av.z);
            As[k4 + 3][row] = to_tf32(av.w);
        }
        {
            float4 bv = *(const float4*)(B + (size_t)(k0 + b_k) * NC + colBase + b_n4);
            Bs[b_k][b_n4 + 0] = to_tf32(bv.x);
            Bs[b_k][b_n4 + 1] = to_tf32(bv.y);
            Bs[b_k][b_n4 + 2] = to_tf32(bv.z);
            Bs[b_k][b_n4 + 3] = to_tf32(bv.w);
        }
        __syncthreads();

#pragma unroll
        for (int ks = 0; ks < 2; ks++) {
            const int k8 = ks * 8;
            uint32_t a[2][4];
#pragma unroll
            for (int mt = 0; mt < 2; mt++) {
                int m0 = wm * 32 + mt * 16 + gid;
                a[mt][0] = __float_as_uint(As[k8 + tig][m0]);
                a[mt][1] = __float_as_uint(As[k8 + tig][m0 + 8]);
                a[mt][2] = __float_as_uint(As[k8 + tig + 4][m0]);
                a[mt][3] = __float_as_uint(As[k8 + tig + 4][m0 + 8]);
            }
            uint32_t b[4][2];
#pragma unroll
            for (int nt = 0; nt < 4; nt++) {
                int n0 = wn * 32 + nt * 8 + gid;
                b[nt][0] = __float_as_uint(Bs[k8 + tig][n0]);
                b[nt][1] = __float_as_uint(Bs[k8 + tig + 4][n0]);
            }
#pragma unroll
            for (int mt = 0; mt < 2; mt++)
#pragma unroll
                for (int nt = 0; nt < 4; nt++) {
                    asm volatile(
                        "mma.sync.aligned.m16n8k8.row.col.f32.tf32.tf32.f32 "
                        "{%0,%1,%2,%3}, {%4,%5,%6,%7}, {%8,%9}, {%0,%1,%2,%3};"
                        : "+f"(acc[mt][nt][0]), "+f"(acc[mt][nt][1]),
                          "+f"(acc[mt][nt][2]), "+f"(acc[mt][nt][3])
                        : "r"(a[mt][0]), "r"(a[mt][1]), "r"(a[mt][2]), "r"(a[mt][3]),
                          "r"(b[nt][0]), "r"(b[nt][1]));
                }
        }
        __syncthreads();
    }

    // epilogue: c frag layout: c0,c1 -> (gid, 2tig), (gid, 2tig+1); c2,c3 -> +8 rows
#pragma unroll
    for (int mt = 0; mt < 2; mt++) {
#pragma unroll
        for (int nt = 0; nt < 4; nt++) {
            int col = colBase + wn * 32 + nt * 8 + 2 * tig;
            float bz0 = bias[col], bz1 = bias[col + 1];
            int r0 = rowBase + wm * 32 + mt * 16 + gid;
            int r1 = r0 + 8;
            float v0 = acc[mt][nt][0] + bz0;
            float v1 = acc[mt][nt][1] + bz1;
            float v2 = acc[mt][nt][2] + bz0;
            float v3 = acc[mt][nt][3] + bz1;
            if (relu) {
                v0 = fmaxf(v0, 0.f); v1 = fmaxf(v1, 0.f);
                v2 = fmaxf(v2, 0.f); v3 = fmaxf(v3, 0.f);
            }
            if (r0 < NND) *(float2*)(out + (size_t)r0 * NC + col) = make_float2(v0, v1);
            if (r1 < NND) *(float2*)(out + (size_t)r1 * NC + col) = make_float2(v2, v3);
        }
    }
}

// ---------------- launch -----------------------------------------------------
extern "C" void kernel_launch(void* const* d_in, const int* in_sizes, int n_in,
                              void* d_out, int out_size)
{
    const float* x   = (const float*)d_in[0];
    const void*  ei  = d_in[1];
    const float* Wl0 = (const float*)d_in[2];
    const float* b0  = (const float*)d_in[3];
    const float* Wr0 = (const float*)d_in[4];
    const float* Wl1 = (const float*)d_in[5];
    const float* b1  = (const float*)d_in[6];
    const float* Wr1 = (const float*)d_in[7];
    const float* Wl2 = (const float*)d_in[8];
    const float* b2  = (const float*)d_in[9];
    const float* Wr2 = (const float*)d_in[10];
    float* out = (float*)d_out;

    // edge decode (dtype-robust) + CSR build
    k_detect<<<1, 32>>>((const int*)ei);
    k_decode<<<(NED + 255) / 256, 256>>>(ei);
    k_init  <<<(NND + 255) / 256, 256>>>();
    k_count <<<(NED + 255) / 256, 256>>>();
    k_scan  <<<1, 1024>>>();
    k_fill  <<<(NED + 255) / 256, 256>>>();

    const int AGG_BLK = 256;
    int aggGrid = (NND * 32 + AGG_BLK - 1) / AGG_BLK;
    int gemmRows = (NND + BM - 1) / BM;

    // layer 0: 128 -> 256, relu.  agg(x) -> g_mean; gemm(g_mean, x) -> g_h1
    k_aggregate<32><<<aggGrid, AGG_BLK>>>(x, 0, 1);
    {
        dim3 g(gemmRows, 256 / BN);
        k_gemm_tc<<<g, 256>>>(1, x, 0, Wl0, Wr0, b0, nullptr, 2, 128, 256, 1);
    }

    // layer 1: 256 -> 256, relu.  agg(g_h1) -> g_mean; gemm(g_mean, g_h1) -> g_h2
    k_aggregate<64><<<aggGrid, AGG_BLK>>>(nullptr, 2, 1);
    {
        dim3 g(gemmRows, 256 / BN);
        k_gemm_tc<<<g, 256>>>(1, nullptr, 2, Wl1, Wr1, b1, nullptr, 3, 256, 256, 1);
    }

    // layer 2: 256 -> 128, no relu.  agg(g_h2) -> g_mean; gemm(g_mean, g_h2) -> out
    k_aggregate<64><<<aggGrid, AGG_BLK>>>(nullptr, 3, 1);
    {
        dim3 g(gemmRows, 128 / BN);
        k_gemm_tc<<<g, 256>>>(1, nullptr, 3, Wl2, Wr2, b2, out, 0, 256, 128, 0);
    }
    (void)in_sizes; (void)n_in; (void)out_size;
}